// round 1
// baseline (speedup 1.0000x reference)
#include <cuda_runtime.h>

namespace {
constexpr int D  = 256;
constexpr int H  = 8;
constexpr int HD = 32;
constexpr int S  = 255;
constexpr int S1 = 256;
constexpr int B  = 4;
constexpr int AOFF = B * S1 * H * HD;  // 262144: basis_outputs size, attn follows
}

// ---------------- device scratch (no allocs allowed) ----------------
__device__ float g_vWT[D * D];     // vW transposed: [k][c]
__device__ float g_W1Ta[D * D];    // eW1[:, :256] transposed: [k][c]
__device__ float g_W1Tb[D * D];    // eW1[:, 256:] transposed: [k][c]
__device__ float g_uk[H * D];      // per-head k-projection folded with wk
__device__ float g_V2[D * H];      // [c][h] : eW2 folded with we, packed for LDS.128
__device__ float g_A[B * S1 * D];  // [b][s][c] row-major (s in 0..254 valid)
__device__ float g_AT[B * D * S1]; // [b][c][s]
__device__ float g_Bt[B * D * S1]; // [b][c][s], includes eb1
__device__ float g_v[B * S1 * D];  // value vectors [b][j][c]
__device__ float g_ks[B * H * S1]; // k-side logit term [b][h][j]

// ---------------- kernel 0a: weight transposes ----------------
__global__ void k_transpose(const float* __restrict__ vW, const float* __restrict__ eW1) {
    int k = blockIdx.x, c = threadIdx.x;
    if (blockIdx.y == 0)      g_vWT [k * D + c] = vW [c * D + k];
    else if (blockIdx.y == 1) g_W1Ta[k * D + c] = eW1[c * 2 * D + k];
    else                      g_W1Tb[k * D + c] = eW1[c * 2 * D + D + k];
}

// ---------------- kernel 0b: fold attention vectors into weights ----------------
__global__ void k_wvec(const float* __restrict__ kW, const float* __restrict__ eW2,
                       const float* __restrict__ aW) {
    int h = blockIdx.x, c = threadIdx.x;
    float ak = 0.f, av = 0.f;
#pragma unroll
    for (int d = 0; d < HD; d++) {
        ak = fmaf(aW[HD + d],     kW [(h * HD + d) * D + c], ak);
        av = fmaf(aW[2 * HD + d], eW2[(h * HD + d) * D + c], av);
    }
    g_uk[h * D + c] = ak;
    g_V2[c * H + h] = av;
}

// ---------------- kernel 1: per-node precompute ----------------
__global__ void __launch_bounds__(256) k_node(
    const float* __restrict__ desc, const float* __restrict__ nve,
    const float* __restrict__ vb,   const float* __restrict__ eb1) {
    int b = blockIdx.x >> 8, s = blockIdx.x & 255, c = threadIdx.x;
    __shared__ float nv[D];
    __shared__ float ds[D];
    nv[c] = nve[(b * S1 + s) * D + c];
    if (s < S) ds[c] = desc[(b * S + s) * D + c];
    __syncthreads();

    // v = nve @ vW.T + vb   (coalesced via transposed weights)
    float acc = vb[c];
#pragma unroll 8
    for (int k = 0; k < D; k++) acc = fmaf(nv[k], g_vWT[k * D + c], acc);
    g_v[(b * S1 + s) * D + c] = acc;

    // ks[b,h,s] = nve_s . uk[h]   (only 8 scalars; threads 0..7)
    if (c < H) {
        float a = 0.f;
        const float* u = &g_uk[c * D];
#pragma unroll 8
        for (int k = 0; k < D; k++) a = fmaf(nv[k], u[k], a);
        g_ks[(b * H + c) * S1 + s] = a;
    }

    // A_s, B_s (+eb1) from desc
    if (s < S) {
        float a = 0.f, bb = eb1[c];
#pragma unroll 4
        for (int k = 0; k < D; k++) {
            a  = fmaf(ds[k], g_W1Ta[k * D + c], a);
            bb = fmaf(ds[k], g_W1Tb[k * D + c], bb);
        }
        g_A [(b * S1 + s) * D + c]  = a;   // row-major for smem row load
        g_AT[(b * D + c) * S1 + s]  = a;   // transposed for CLS row (i==0)
        g_Bt[(b * D + c) * S1 + s]  = bb;  // transposed for coalesced j-column reads
    }
}

// ---------------- kernel 2: edges + softmax + context ----------------
__global__ void __launch_bounds__(256) k_main(
    const float* __restrict__ lng, const float* __restrict__ lnb,
    float* __restrict__ out) {
    int b = blockIdx.x >> 8, i = blockIdx.x & 255;
    int t = threadIdx.x;

    __shared__ float  As[D];
    __shared__ float2 gb[D];
    __shared__ float4 V2s[2 * D];       // [c][h0..3],[c][h4..7]
    __shared__ float  attn_s[H][S1];
    __shared__ float  red[H];

    As[t] = (i > 0) ? g_A[(b * S1 + (i - 1)) * D + t] : 0.f;
    gb[t] = make_float2(lng[t], lnb[t]);
    {
        const float4* src = (const float4*)g_V2;
        V2s[t]       = src[t];
        V2s[t + 256] = src[t + 256];
    }
    __syncthreads();

    float lg[H];
#pragma unroll
    for (int h = 0; h < H; h++) lg[h] = -1e30f;  // j==0 column masked

    if (t > 0) {
        int jn = t - 1;
        const float* BtC = g_Bt + b * D * S1 + jn;
        const float* AtC = g_AT + b * D * S1 + jn;

        // pass 1: LN statistics of x_c = A_i[c] + B_j[c] (+eb1)
        float sum = 0.f, sumsq = 0.f;
        if (i > 0) {
#pragma unroll 8
            for (int c = 0; c < D; c++) {
                float x = As[c] + BtC[c * S1];
                sum += x; sumsq = fmaf(x, x, sumsq);
            }
        } else {
#pragma unroll 8
            for (int c = 0; c < D; c++) {
                float x = AtC[c * S1] + BtC[c * S1];
                sum += x; sumsq = fmaf(x, x, sumsq);
            }
        }
        const float invD = 1.0f / D;
        float mu   = sum * invD;
        float var  = fmaf(sumsq, invD, -mu * mu);
        float rstd = rsqrtf(var + 1e-5f);

        // pass 2: y = relu(LN(x)); 8 head dots with V2
        float a0=0,a1=0,a2=0,a3=0,a4=0,a5=0,a6=0,a7=0;
        if (i > 0) {
#pragma unroll 4
            for (int c = 0; c < D; c++) {
                float x = As[c] + BtC[c * S1];
                float2 g2 = gb[c];
                float y = fmaxf(fmaf((x - mu) * rstd, g2.x, g2.y), 0.f);
                float4 va = V2s[2 * c], vb4 = V2s[2 * c + 1];
                a0 = fmaf(y, va.x,  a0); a1 = fmaf(y, va.y,  a1);
                a2 = fmaf(y, va.z,  a2); a3 = fmaf(y, va.w,  a3);
                a4 = fmaf(y, vb4.x, a4); a5 = fmaf(y, vb4.y, a5);
                a6 = fmaf(y, vb4.z, a6); a7 = fmaf(y, vb4.w, a7);
            }
        } else {
#pragma unroll 4
            for (int c = 0; c < D; c++) {
                float x = AtC[c * S1] + BtC[c * S1];
                float2 g2 = gb[c];
                float y = fmaxf(fmaf((x - mu) * rstd, g2.x, g2.y), 0.f);
                float4 va = V2s[2 * c], vb4 = V2s[2 * c + 1];
                a0 = fmaf(y, va.x,  a0); a1 = fmaf(y, va.y,  a1);
                a2 = fmaf(y, va.z,  a2); a3 = fmaf(y, va.w,  a3);
                a4 = fmaf(y, vb4.x, a4); a5 = fmaf(y, vb4.y, a5);
                a6 = fmaf(y, vb4.z, a6); a7 = fmaf(y, vb4.w, a7);
            }
        }
        const float* ksp = g_ks + b * H * S1 + t;
        lg[0] = a0 + ksp[0*S1]; lg[1] = a1 + ksp[1*S1];
        lg[2] = a2 + ksp[2*S1]; lg[3] = a3 + ksp[3*S1];
        lg[4] = a4 + ksp[4*S1]; lg[5] = a5 + ksp[5*S1];
        lg[6] = a6 + ksp[6*S1]; lg[7] = a7 + ksp[7*S1];
    }

#pragma unroll
    for (int h = 0; h < H; h++) attn_s[h][t] = lg[h];
    __syncthreads();

    // ---- softmax over j: warp w owns head w ----
    int w = t >> 5, l = t & 31;
    float m = -1e30f;
#pragma unroll
    for (int k = 0; k < 8; k++) m = fmaxf(m, attn_s[w][l + 32 * k]);
#pragma unroll
    for (int o = 16; o > 0; o >>= 1) m = fmaxf(m, __shfl_xor_sync(0xffffffffu, m, o));
    if (l == 0) red[w] = m;
    __syncthreads();

    float p[H];
#pragma unroll
    for (int h = 0; h < H; h++) {
        p[h] = (t > 0) ? __expf(lg[h] - red[h]) : 0.f;
        attn_s[h][t] = p[h];
    }
    __syncthreads();

    float sm = 0.f;
#pragma unroll
    for (int k = 0; k < 8; k++) sm += attn_s[w][l + 32 * k];
#pragma unroll
    for (int o = 16; o > 0; o >>= 1) sm += __shfl_xor_sync(0xffffffffu, sm, o);
    if (l == 0) red[w] = 1.0f / sm;
    __syncthreads();

    float* arow = out + AOFF + ((b * H) * S1 + i) * S1 + t;  // attn[b][h][i][j]
#pragma unroll
    for (int h = 0; h < H; h++) {
        float a = p[h] * red[h];
        attn_s[h][t] = a;
        arow[h * S1 * S1] = a;
    }
    __syncthreads();

    // ---- ctx = attn @ v ; thread t = (h, d) output channel ----
    int hh = t >> 5;
    float acc = 0.f;
    const float* vp = g_v + b * S1 * D + t;
#pragma unroll 8
    for (int j = 0; j < S1; j++) acc = fmaf(attn_s[hh][j], vp[j * D], acc);
    out[(b * S1 + i) * D + t] = acc;  // basis_outputs[b][i][h][d]
}

// ---------------- launch ----------------
extern "C" void kernel_launch(void* const* d_in, const int* in_sizes, int n_in,
                              void* d_out, int out_size) {
    (void)in_sizes; (void)n_in; (void)out_size;
    const float* desc = (const float*)d_in[0];
    const float* nve  = (const float*)d_in[1];
    const float* kW   = (const float*)d_in[4];
    const float* vW   = (const float*)d_in[6];
    const float* vb   = (const float*)d_in[7];
    const float* eW1  = (const float*)d_in[8];
    const float* eb1  = (const float*)d_in[9];
    const float* lng  = (const float*)d_in[10];
    const float* lnb  = (const float*)d_in[11];
    const float* eW2  = (const float*)d_in[12];
    const float* aW   = (const float*)d_in[14];
    float* out = (float*)d_out;

    k_transpose<<<dim3(256, 3), 256>>>(vW, eW1);
    k_wvec<<<H, 256>>>(kW, eW2, aW);
    k_node<<<B * S1, 256>>>(desc, nve, vb, eb1);
    k_main<<<B * S1, 256>>>(lng, lnb, out);
}

// round 2
// speedup vs baseline: 1.1136x; 1.1136x over previous
#include <cuda_runtime.h>

namespace {
constexpr int D  = 256;
constexpr int H  = 8;
constexpr int HD = 32;
constexpr int S  = 255;
constexpr int S1 = 256;
constexpr int B  = 4;
constexpr int AOFF = B * S1 * H * HD;  // basis_outputs elements; attn follows
constexpr int ITILE = 4;
}

// ---------------- device scratch ----------------
__device__ float g_vWT[D * D];
__device__ float g_W1Ta[D * D];
__device__ float g_W1Tb[D * D];
__device__ float g_uk[H * D];
__device__ float g_V2[D * H];        // [c][h], float4-friendly
__device__ float g_A[B * S1 * D];    // [b][s][c]  (row 255 stays zero)
__device__ float g_AT[B * D * S1];   // [b][c][s]
__device__ float g_Bt[B * D * S1];   // [b][c][s], includes eb1
__device__ float g_Brow[B * S1 * D]; // [b][s][c], includes eb1 (row 255 zero)
__device__ float g_v[B * S1 * D];    // [b][j][c]
__device__ float g_ks[B * H * S1];
__device__ float g_SA[B * S1];       // per-node sums of A
__device__ float g_QA[B * S1];       // per-node sumsq of A
__device__ float g_SB[B * S1];
__device__ float g_QB[B * S1];
__device__ float g_G[B * S1 * S1];   // G[b][i][j] = A_i . B_j

// ---------------- kernel 0a: weight transposes ----------------
__global__ void k_transpose(const float* __restrict__ vW, const float* __restrict__ eW1) {
    int k = blockIdx.x, c = threadIdx.x;
    if (blockIdx.y == 0)      g_vWT [k * D + c] = vW [c * D + k];
    else if (blockIdx.y == 1) g_W1Ta[k * D + c] = eW1[c * 2 * D + k];
    else                      g_W1Tb[k * D + c] = eW1[c * 2 * D + D + k];
}

// ---------------- kernel 0b: fold attention vectors ----------------
__global__ void k_wvec(const float* __restrict__ kW, const float* __restrict__ eW2,
                       const float* __restrict__ aW) {
    int h = blockIdx.x, c = threadIdx.x;
    float ak = 0.f, av = 0.f;
#pragma unroll
    for (int d = 0; d < HD; d++) {
        ak = fmaf(aW[HD + d],     kW [(h * HD + d) * D + c], ak);
        av = fmaf(aW[2 * HD + d], eW2[(h * HD + d) * D + c], av);
    }
    g_uk[h * D + c] = ak;
    g_V2[c * H + h] = av;
}

// ---------------- kernel 1: per-node precompute + stats ----------------
__global__ void __launch_bounds__(256) k_node(
    const float* __restrict__ desc, const float* __restrict__ nve,
    const float* __restrict__ vb,   const float* __restrict__ eb1) {
    int b = blockIdx.x >> 8, s = blockIdx.x & 255, c = threadIdx.x;
    __shared__ float nv[D];
    __shared__ float ds[D];
    nv[c] = nve[(b * S1 + s) * D + c];
    if (s < S) ds[c] = desc[(b * S + s) * D + c];
    __syncthreads();

    float acc = vb[c];
#pragma unroll 8
    for (int k = 0; k < D; k++) acc = fmaf(nv[k], g_vWT[k * D + c], acc);
    g_v[(b * S1 + s) * D + c] = acc;

    if (c < H) {
        float a = 0.f;
        const float* u = &g_uk[c * D];
#pragma unroll 8
        for (int k = 0; k < D; k++) a = fmaf(nv[k], u[k], a);
        g_ks[(b * H + c) * S1 + s] = a;
    }

    float a = 0.f, bbv = 0.f;
    if (s < S) {
        bbv = eb1[c];
#pragma unroll 4
        for (int k = 0; k < D; k++) {
            a   = fmaf(ds[k], g_W1Ta[k * D + c], a);
            bbv = fmaf(ds[k], g_W1Tb[k * D + c], bbv);
        }
        g_A   [(b * S1 + s) * D + c] = a;
        g_AT  [(b * D + c) * S1 + s] = a;
        g_Bt  [(b * D + c) * S1 + s] = bbv;
        g_Brow[(b * S1 + s) * D + c] = bbv;
    }

    // block reduction for per-node LN stats
    __shared__ float4 rbuf[256];
    rbuf[c] = make_float4(a, a * a, bbv, bbv * bbv);
    __syncthreads();
#pragma unroll
    for (int st = 128; st > 0; st >>= 1) {
        if (c < st) {
            float4 o = rbuf[c + st], m = rbuf[c];
            rbuf[c] = make_float4(m.x + o.x, m.y + o.y, m.z + o.z, m.w + o.w);
        }
        __syncthreads();
    }
    if (c == 0) {
        float4 r = rbuf[0];
        g_SA[b * S1 + s] = r.x; g_QA[b * S1 + s] = r.y;
        g_SB[b * S1 + s] = r.z; g_QB[b * S1 + s] = r.w;
    }
}

// ---------------- kernel 1b: G[b][i][j] = A_i . B_j (tiled NT sgemm) ----------------
__global__ void __launch_bounds__(256) k_gemmG() {
    int b  = blockIdx.z;
    int i0 = blockIdx.y * 32;
    int j0 = blockIdx.x * 32;
    __shared__ float As[32][33];
    __shared__ float Bs[32][33];
    int t = threadIdx.x;
    int jj = t & 31, ii4 = (t >> 5) * 4;
    int lr = t >> 3, lc = (t & 7) * 4;
    float acc0 = 0.f, acc1 = 0.f, acc2 = 0.f, acc3 = 0.f;

    for (int kc = 0; kc < D; kc += 32) {
        float4 fa = *(const float4*)&g_A   [(b * S1 + i0 + lr) * D + kc + lc];
        float4 fb = *(const float4*)&g_Brow[(b * S1 + j0 + lr) * D + kc + lc];
        As[lr][lc] = fa.x; As[lr][lc+1] = fa.y; As[lr][lc+2] = fa.z; As[lr][lc+3] = fa.w;
        Bs[lr][lc] = fb.x; Bs[lr][lc+1] = fb.y; Bs[lr][lc+2] = fb.z; Bs[lr][lc+3] = fb.w;
        __syncthreads();
#pragma unroll
        for (int kk = 0; kk < 32; kk++) {
            float bv = Bs[jj][kk];
            acc0 = fmaf(As[ii4 + 0][kk], bv, acc0);
            acc1 = fmaf(As[ii4 + 1][kk], bv, acc1);
            acc2 = fmaf(As[ii4 + 2][kk], bv, acc2);
            acc3 = fmaf(As[ii4 + 3][kk], bv, acc3);
        }
        __syncthreads();
    }
    float* gp = &g_G[(b * S1 + i0 + ii4) * S1 + j0 + jj];
    gp[0 * S1] = acc0; gp[1 * S1] = acc1; gp[2 * S1] = acc2; gp[3 * S1] = acc3;
}

// ---------------- kernel 2: edges + softmax + context (4 rows / block) ----------------
template <bool CLS>
__device__ __forceinline__ void edge_loop(
    const float* __restrict__ BtC, const float* __restrict__ AtC,
    const float (*As4)[D], const float2* gb, const float4* V2s,
    const float* mu, const float* rstd, float acc[ITILE][H]) {
#pragma unroll 4
    for (int c = 0; c < D; c++) {
        float btv = __ldg(&BtC[c * S1]);
        float a0v = CLS ? __ldg(&AtC[c * S1]) : As4[0][c];
        float2 g2 = gb[c];
        float4 va = V2s[2 * c], vb4 = V2s[2 * c + 1];
#pragma unroll
        for (int r = 0; r < ITILE; r++) {
            float x = ((r == 0) ? a0v : As4[r][c]) + btv;
            float y = fmaxf(fmaf((x - mu[r]) * rstd[r], g2.x, g2.y), 0.f);
            acc[r][0] = fmaf(y, va.x,  acc[r][0]);
            acc[r][1] = fmaf(y, va.y,  acc[r][1]);
            acc[r][2] = fmaf(y, va.z,  acc[r][2]);
            acc[r][3] = fmaf(y, va.w,  acc[r][3]);
            acc[r][4] = fmaf(y, vb4.x, acc[r][4]);
            acc[r][5] = fmaf(y, vb4.y, acc[r][5]);
            acc[r][6] = fmaf(y, vb4.z, acc[r][6]);
            acc[r][7] = fmaf(y, vb4.w, acc[r][7]);
        }
    }
}

__global__ void __launch_bounds__(256) k_main(
    const float* __restrict__ lng, const float* __restrict__ lnb,
    float* __restrict__ out) {
    int bid = blockIdx.x;
    int b = bid >> 6, i0 = (bid & 63) * ITILE;
    int t = threadIdx.x;
    bool hasCls = (i0 == 0);

    __shared__ float  As4[ITILE][D];
    __shared__ float2 gb[D];
    __shared__ float4 V2s[2 * D];
    __shared__ float  attn_s[ITILE][H][S1];
    __shared__ float  red[H];

#pragma unroll
    for (int r = 0; r < ITILE; r++) {
        int i = i0 + r;
        As4[r][t] = (i > 0) ? g_A[(b * S1 + i - 1) * D + t] : 0.f;
    }
    gb[t] = make_float2(lng[t], lnb[t]);
    {
        const float4* src = (const float4*)g_V2;
        V2s[t] = src[t]; V2s[t + 256] = src[t + 256];
    }
    __syncthreads();

    int jn = (t > 0) ? t - 1 : 0;
    float sb = g_SB[b * S1 + jn], qb = g_QB[b * S1 + jn];
    float mu[ITILE], rstd[ITILE];
#pragma unroll
    for (int r = 0; r < ITILE; r++) {
        int i = i0 + r;
        float sa, qa, gij;
        if (i == 0) {
            sa = g_SA[b * S1 + jn]; qa = g_QA[b * S1 + jn];
            gij = g_G[(b * S1 + jn) * S1 + jn];
        } else {
            sa = g_SA[b * S1 + i - 1]; qa = g_QA[b * S1 + i - 1];
            gij = g_G[(b * S1 + i - 1) * S1 + jn];
        }
        const float invD = 1.0f / D;
        float m = (sa + sb) * invD;
        float var = fmaf(2.f, gij, qa + qb) * invD - m * m;
        mu[r] = m; rstd[r] = rsqrtf(var + 1e-5f);
    }

    const float* BtC = g_Bt + b * D * S1 + jn;
    const float* AtC = g_AT + b * D * S1 + jn;

    float acc[ITILE][H];
#pragma unroll
    for (int r = 0; r < ITILE; r++)
#pragma unroll
        for (int h = 0; h < H; h++) acc[r][h] = 0.f;

    if (hasCls) edge_loop<true >(BtC, AtC, As4, gb, V2s, mu, rstd, acc);
    else        edge_loop<false>(BtC, AtC, As4, gb, V2s, mu, rstd, acc);

    const float* ksp = g_ks + b * H * S1 + t;
#pragma unroll
    for (int r = 0; r < ITILE; r++)
#pragma unroll
        for (int h = 0; h < H; h++) {
            float l = (t > 0) ? acc[r][h] + ksp[h * S1] : -1e30f;
            acc[r][h] = l;
            attn_s[r][h][t] = l;
        }
    __syncthreads();

    int w = t >> 5, l = t & 31;
#pragma unroll
    for (int r = 0; r < ITILE; r++) {
        float m = -1e30f;
#pragma unroll
        for (int k = 0; k < 8; k++) m = fmaxf(m, attn_s[r][w][l + 32 * k]);
#pragma unroll
        for (int o = 16; o > 0; o >>= 1) m = fmaxf(m, __shfl_xor_sync(0xffffffffu, m, o));
        if (l == 0) red[w] = m;
        __syncthreads();
#pragma unroll
        for (int h = 0; h < H; h++)
            attn_s[r][h][t] = __expf(acc[r][h] - red[h]);
        __syncthreads();
        float sm = 0.f;
#pragma unroll
        for (int k = 0; k < 8; k++) sm += attn_s[r][w][l + 32 * k];
#pragma unroll
        for (int o = 16; o > 0; o >>= 1) sm += __shfl_xor_sync(0xffffffffu, sm, o);
        if (l == 0) red[w] = 1.0f / sm;
        __syncthreads();
        float* arow = out + AOFF + ((b * H) * S1 + (i0 + r)) * S1 + t;
#pragma unroll
        for (int h = 0; h < H; h++) {
            float a = attn_s[r][h][t] * red[h];
            attn_s[r][h][t] = a;
            arow[h * S1 * S1] = a;
        }
        __syncthreads();
    }

    // ctx = attn @ v ; thread t = (h, d); v_j loaded once, feeds 4 rows
    int hh = t >> 5;
    const float* vp = g_v + b * S1 * D + t;
    float c0 = 0.f, c1 = 0.f, c2 = 0.f, c3 = 0.f;
#pragma unroll 4
    for (int j = 0; j < S1; j++) {
        float vj = vp[j * D];
        c0 = fmaf(attn_s[0][hh][j], vj, c0);
        c1 = fmaf(attn_s[1][hh][j], vj, c1);
        c2 = fmaf(attn_s[2][hh][j], vj, c2);
        c3 = fmaf(attn_s[3][hh][j], vj, c3);
    }
    out[(b * S1 + i0 + 0) * D + t] = c0;
    out[(b * S1 + i0 + 1) * D + t] = c1;
    out[(b * S1 + i0 + 2) * D + t] = c2;
    out[(b * S1 + i0 + 3) * D + t] = c3;
}

// ---------------- launch ----------------
extern "C" void kernel_launch(void* const* d_in, const int* in_sizes, int n_in,
                              void* d_out, int out_size) {
    (void)in_sizes; (void)n_in; (void)out_size;
    const float* desc = (const float*)d_in[0];
    const float* nve  = (const float*)d_in[1];
    const float* kW   = (const float*)d_in[4];
    const float* vW   = (const float*)d_in[6];
    const float* vb   = (const float*)d_in[7];
    const float* eW1  = (const float*)d_in[8];
    const float* eb1  = (const float*)d_in[9];
    const float* lng  = (const float*)d_in[10];
    const float* lnb  = (const float*)d_in[11];
    const float* eW2  = (const float*)d_in[12];
    const float* aW   = (const float*)d_in[14];
    float* out = (float*)d_out;

    k_transpose<<<dim3(256, 3), 256>>>(vW, eW1);
    k_wvec<<<H, 256>>>(kW, eW2, aW);
    k_node<<<B * S1, 256>>>(desc, nve, vb, eb1);
    k_gemmG<<<dim3(8, 8, B), 256>>>();
    k_main<<<B * S1 / ITILE, 256>>>(lng, lnb, out);
}

// round 4
// speedup vs baseline: 1.2114x; 1.0878x over previous
#include <cuda_runtime.h>

typedef unsigned long long ull;

__device__ __forceinline__ ull ffma2(ull a, ull b, ull c) {
    ull d; asm("fma.rn.f32x2 %0, %1, %2, %3;" : "=l"(d) : "l"(a), "l"(b), "l"(c)); return d;
}
__device__ __forceinline__ ull fadd2(ull a, ull b) {
    ull d; asm("add.rn.f32x2 %0, %1, %2;" : "=l"(d) : "l"(a), "l"(b)); return d;
}
__device__ __forceinline__ ull fpack(float lo, float hi) {
    ull d; asm("mov.b64 %0, {%1, %2};" : "=l"(d) : "f"(lo), "f"(hi)); return d;
}
__device__ __forceinline__ void funpack(ull v, float& lo, float& hi) {
    asm("mov.b64 {%0, %1}, %2;" : "=f"(lo), "=f"(hi) : "l"(v));
}

namespace {
constexpr int D  = 256;
constexpr int H  = 8;
constexpr int HD = 32;
constexpr int S  = 255;
constexpr int S1 = 256;
constexpr int B  = 4;
constexpr int AOFF = B * S1 * H * HD;
constexpr int ITILE = 4;
constexpr int STILE = 8;   // rows per k_node block
}

// ---------------- device scratch ----------------
__device__ float  g_vWT[D * D];
__device__ float  g_W1Ta[D * D];
__device__ float  g_W1Tb[D * D];
__device__ float  g_uk[H * D];
__device__ float  g_V2[D * H];          // [c][h]
__device__ float  g_A[B * S1 * D];      // [b][s][c]
__device__ float  g_Brow[B * S1 * D];   // [b][s][c] incl eb1
__device__ float2 g_At2[B * (D/2) * S1];// [(b,c2)][s] = (A[2c2][s], A[2c2+1][s])
__device__ float2 g_Bt2[B * (D/2) * S1];
__device__ float  g_v[B * S1 * D];
__device__ float  g_ks[B * H * S1];
__device__ float  g_SA[B * S1];
__device__ float  g_QA[B * S1];
__device__ float  g_SB[B * S1];
__device__ float  g_QB[B * S1];
__device__ float  g_G[B * S1 * S1];     // A_i . B_j

// ---------------- kernel 0a: weight transposes ----------------
__global__ void k_transpose(const float* __restrict__ vW, const float* __restrict__ eW1) {
    int k = blockIdx.x, c = threadIdx.x;
    if (blockIdx.y == 0)      g_vWT [k * D + c] = vW [c * D + k];
    else if (blockIdx.y == 1) g_W1Ta[k * D + c] = eW1[c * 2 * D + k];
    else                      g_W1Tb[k * D + c] = eW1[c * 2 * D + D + k];
}

// ---------------- kernel 0b: fold attention vectors ----------------
__global__ void k_wvec(const float* __restrict__ kW, const float* __restrict__ eW2,
                       const float* __restrict__ aW) {
    int h = blockIdx.x, c = threadIdx.x;
    float ak = 0.f, av = 0.f;
#pragma unroll
    for (int d = 0; d < HD; d++) {
        ak = fmaf(aW[HD + d],     kW [(h * HD + d) * D + c], ak);
        av = fmaf(aW[2 * HD + d], eW2[(h * HD + d) * D + c], av);
    }
    g_uk[h * D + c] = ak;
    g_V2[c * H + h] = av;
}

// ---------------- kernel 1: per-node precompute (8 rows/block) ----------------
__global__ void __launch_bounds__(256) k_node(
    const float* __restrict__ desc, const float* __restrict__ nve,
    const float* __restrict__ vb,   const float* __restrict__ eb1) {
    int b = blockIdx.x >> 5, s0 = (blockIdx.x & 31) * STILE, c = threadIdx.x;
    __shared__ float nv[STILE][D];
    __shared__ float ds[STILE][D];
    __shared__ float4 wr[8];

#pragma unroll
    for (int r = 0; r < STILE; r++) {
        nv[r][c] = nve[(b * S1 + s0 + r) * D + c];
        ds[r][c] = (s0 + r < S) ? desc[(b * S + s0 + r) * D + c] : 0.f;
    }
    __syncthreads();

    float accv[STILE], acca[STILE], accb[STILE];
    float vbc = vb[c], eb1c = eb1[c];
#pragma unroll
    for (int r = 0; r < STILE; r++) { accv[r] = vbc; acca[r] = 0.f; accb[r] = eb1c; }

#pragma unroll 2
    for (int k = 0; k < D; k++) {
        float w0 = g_vWT [k * D + c];
        float w1 = g_W1Ta[k * D + c];
        float w2 = g_W1Tb[k * D + c];
#pragma unroll
        for (int r = 0; r < STILE; r++) {
            float n = nv[r][k], d = ds[r][k];
            accv[r] = fmaf(n, w0, accv[r]);
            acca[r] = fmaf(d, w1, acca[r]);
            accb[r] = fmaf(d, w2, accb[r]);
        }
    }

    int lane = c & 31, w = c >> 5;
#pragma unroll
    for (int r = 0; r < STILE; r++) {
        int s = s0 + r;
        bool valid = (s < S);
        float a  = valid ? acca[r] : 0.f;
        float bb = valid ? accb[r] : 0.f;
        g_v   [(b * S1 + s) * D + c] = accv[r];
        g_A   [(b * S1 + s) * D + c] = a;
        g_Brow[(b * S1 + s) * D + c] = bb;
        ((float*)g_At2)[((b * 128 + (c >> 1)) * S1 + s) * 2 + (c & 1)] = a;
        ((float*)g_Bt2)[((b * 128 + (c >> 1)) * S1 + s) * 2 + (c & 1)] = bb;

        // stats reduction
        float4 v4 = make_float4(a, a * a, bb, bb * bb);
#pragma unroll
        for (int o = 16; o > 0; o >>= 1) {
            v4.x += __shfl_xor_sync(0xffffffffu, v4.x, o);
            v4.y += __shfl_xor_sync(0xffffffffu, v4.y, o);
            v4.z += __shfl_xor_sync(0xffffffffu, v4.z, o);
            v4.w += __shfl_xor_sync(0xffffffffu, v4.w, o);
        }
        if (lane == 0) wr[w] = v4;
        __syncthreads();
        if (c == 0) {
            float4 t = wr[0];
#pragma unroll
            for (int q = 1; q < 8; q++) {
                float4 o = wr[q];
                t.x += o.x; t.y += o.y; t.z += o.z; t.w += o.w;
            }
            g_SA[b * S1 + s] = t.x; g_QA[b * S1 + s] = t.y;
            g_SB[b * S1 + s] = t.z; g_QB[b * S1 + s] = t.w;
        }
        __syncthreads();
    }

    // ks: warp w handles row s0+w, all 8 heads
    {
        float kacc[H];
#pragma unroll
        for (int h = 0; h < H; h++) kacc[h] = 0.f;
        for (int k = lane; k < D; k += 32) {
            float n = nv[w][k];
#pragma unroll
            for (int h = 0; h < H; h++) kacc[h] = fmaf(n, g_uk[h * D + k], kacc[h]);
        }
#pragma unroll
        for (int h = 0; h < H; h++) {
#pragma unroll
            for (int o = 16; o > 0; o >>= 1)
                kacc[h] += __shfl_xor_sync(0xffffffffu, kacc[h], o);
            if (lane == 0) g_ks[(b * H + h) * S1 + s0 + w] = kacc[h];
        }
    }
}

// ---------------- kernel 1b: G = A . B^T, 64x32 tiles ----------------
__global__ void __launch_bounds__(256) k_gemmG() {
    int b  = blockIdx.z;
    int i0 = blockIdx.y * 64;
    int j0 = blockIdx.x * 32;
    __shared__ float As[32][72];   // [kk][ii], 72 pad keeps float4 alignment
    __shared__ float Bs[32][33];
    int t = threadIdx.x;
    int jj = t & 31, ig = t >> 5;          // warp ig covers i rows ig*8..ig*8+7
    float acc[8];
#pragma unroll
    for (int m = 0; m < 8; m++) acc[m] = 0.f;

    int arow = t >> 2, akq = (t & 3) * 8;  // A: 64 rows x 32 k, 8 elems/thread
    int brow = t >> 3, bkq = (t & 7) * 4;  // B: 32 rows x 32 k, 4 elems/thread

    for (int kc = 0; kc < D; kc += 32) {
        float4 fa0 = *(const float4*)&g_A[(b * S1 + i0 + arow) * D + kc + akq];
        float4 fa1 = *(const float4*)&g_A[(b * S1 + i0 + arow) * D + kc + akq + 4];
        float4 fb  = *(const float4*)&g_Brow[(b * S1 + j0 + brow) * D + kc + bkq];
        As[akq + 0][arow] = fa0.x; As[akq + 1][arow] = fa0.y;
        As[akq + 2][arow] = fa0.z; As[akq + 3][arow] = fa0.w;
        As[akq + 4][arow] = fa1.x; As[akq + 5][arow] = fa1.y;
        As[akq + 6][arow] = fa1.z; As[akq + 7][arow] = fa1.w;
        Bs[bkq + 0][brow] = fb.x; Bs[bkq + 1][brow] = fb.y;
        Bs[bkq + 2][brow] = fb.z; Bs[bkq + 3][brow] = fb.w;
        __syncthreads();
#pragma unroll
        for (int kk = 0; kk < 32; kk++) {
            float bv = Bs[kk][jj];
            float4 a0 = *(const float4*)&As[kk][ig * 8];
            float4 a1 = *(const float4*)&As[kk][ig * 8 + 4];
            acc[0] = fmaf(a0.x, bv, acc[0]); acc[1] = fmaf(a0.y, bv, acc[1]);
            acc[2] = fmaf(a0.z, bv, acc[2]); acc[3] = fmaf(a0.w, bv, acc[3]);
            acc[4] = fmaf(a1.x, bv, acc[4]); acc[5] = fmaf(a1.y, bv, acc[5]);
            acc[6] = fmaf(a1.z, bv, acc[6]); acc[7] = fmaf(a1.w, bv, acc[7]);
        }
        __syncthreads();
    }
#pragma unroll
    for (int m = 0; m < 8; m++)
        g_G[(b * S1 + i0 + ig * 8 + m) * S1 + j0 + jj] = acc[m];
}

// ---------------- kernel 2: edges + softmax + context ----------------
template <bool CLS>
__device__ __forceinline__ void edge_loop(
    const long long* __restrict__ btp, const long long* __restrict__ atp,
    const float (*As4)[D], const ull* gp2, const ull* bp2,
    const ulonglong2* V2u, const ull* rstd2, const ull* nmu2,
    ull acc01[ITILE], ull acc23[ITILE], ull acc45[ITILE], ull acc67[ITILE]) {
#pragma unroll 2
    for (int c2 = 0; c2 < D / 2; c2++) {
        ull bt2 = (ull)btp[c2 * S1];
        ull acls = 0;
        if (CLS) acls = (ull)atp[c2 * S1];
        ull g2 = gp2[c2], b2 = bp2[c2];
        ulonglong2 p0 = V2u[4 * c2 + 0], p1 = V2u[4 * c2 + 1];
        ulonglong2 p2 = V2u[4 * c2 + 2], p3 = V2u[4 * c2 + 3];
#pragma unroll
        for (int r = 0; r < ITILE; r++) {
            ull a2 = (CLS && r == 0) ? acls : *(const ull*)&As4[r][2 * c2];
            ull x2 = fadd2(a2, bt2);
            ull t2 = ffma2(x2, rstd2[r], nmu2[r]);
            ull y2 = ffma2(t2, g2, b2);
            float y0, y1; funpack(y2, y0, y1);
            y0 = fmaxf(y0, 0.f); y1 = fmaxf(y1, 0.f);
            ull yy0 = fpack(y0, y0), yy1 = fpack(y1, y1);
            acc01[r] = ffma2(yy0, p0.x, acc01[r]);
            acc23[r] = ffma2(yy0, p0.y, acc23[r]);
            acc45[r] = ffma2(yy0, p1.x, acc45[r]);
            acc67[r] = ffma2(yy0, p1.y, acc67[r]);
            acc01[r] = ffma2(yy1, p2.x, acc01[r]);
            acc23[r] = ffma2(yy1, p2.y, acc23[r]);
            acc45[r] = ffma2(yy1, p3.x, acc45[r]);
            acc67[r] = ffma2(yy1, p3.y, acc67[r]);
        }
    }
}

__global__ void __launch_bounds__(256) k_main(
    const float* __restrict__ lng, const float* __restrict__ lnb,
    float* __restrict__ out) {
    int bid = blockIdx.x;
    int b = bid >> 6, i0 = (bid & 63) * ITILE;
    int t = threadIdx.x;
    bool hasCls = (i0 == 0);

    __shared__ float As4[ITILE][D];
    __shared__ ull gp2[D / 2];
    __shared__ ull bp2[D / 2];
    __shared__ ulonglong2 V2u[2 * D];
    __shared__ float attn_s[ITILE][H][S1];
    __shared__ float red[H];

#pragma unroll
    for (int r = 0; r < ITILE; r++) {
        int i = i0 + r;
        As4[r][t] = (i > 0) ? g_A[(b * S1 + i - 1) * D + t] : 0.f;
    }
    if (t < 128) {
        gp2[t] = fpack(lng[2 * t], lng[2 * t + 1]);
        bp2[t] = fpack(lnb[2 * t], lnb[2 * t + 1]);
    }
    {
        const ulonglong2* src = (const ulonglong2*)g_V2;
        V2u[t] = src[t]; V2u[t + 256] = src[t + 256];
    }
    __syncthreads();

    int jn = (t > 0) ? t - 1 : 0;
    float sb = g_SB[b * S1 + jn], qb = g_QB[b * S1 + jn];
    ull rstd2[ITILE], nmu2[ITILE];
#pragma unroll
    for (int r = 0; r < ITILE; r++) {
        int i = i0 + r;
        float sa, qa, gij;
        if (i == 0) {
            sa = g_SA[b * S1 + jn]; qa = g_QA[b * S1 + jn];
            gij = g_G[(b * S1 + jn) * S1 + jn];
        } else {
            sa = g_SA[b * S1 + i - 1]; qa = g_QA[b * S1 + i - 1];
            gij = g_G[(b * S1 + i - 1) * S1 + jn];
        }
        const float invD = 1.0f / D;
        float m = (sa + sb) * invD;
        float var = fmaf(2.f, gij, qa + qb) * invD - m * m;
        float rs = rsqrtf(var + 1e-5f);
        rstd2[r] = fpack(rs, rs);
        float nm = -m * rs;
        nmu2[r] = fpack(nm, nm);
    }

    const long long* btp = (const long long*)g_Bt2 + (long long)(b * 128) * S1 + jn;
    const long long* atp = (const long long*)g_At2 + (long long)(b * 128) * S1 + jn;

    ull acc01[ITILE], acc23[ITILE], acc45[ITILE], acc67[ITILE];
    ull z = fpack(0.f, 0.f);
#pragma unroll
    for (int r = 0; r < ITILE; r++) { acc01[r] = z; acc23[r] = z; acc45[r] = z; acc67[r] = z; }

    if (hasCls) edge_loop<true >(btp, atp, As4, gp2, bp2, V2u, rstd2, nmu2, acc01, acc23, acc45, acc67);
    else        edge_loop<false>(btp, atp, As4, gp2, bp2, V2u, rstd2, nmu2, acc01, acc23, acc45, acc67);

    const float* ksp = g_ks + b * H * S1 + t;
    float lg[ITILE][H];
#pragma unroll
    for (int r = 0; r < ITILE; r++) {
        float l0, l1, l2, l3, l4, l5, l6, l7;
        funpack(acc01[r], l0, l1); funpack(acc23[r], l2, l3);
        funpack(acc45[r], l4, l5); funpack(acc67[r], l6, l7);
        float hv[H] = {l0, l1, l2, l3, l4, l5, l6, l7};
#pragma unroll
        for (int h = 0; h < H; h++) {
            float l = (t > 0) ? hv[h] + ksp[h * S1] : -1e30f;
            lg[r][h] = l;
            attn_s[r][h][t] = l;
        }
    }
    __syncthreads();

    int w = t >> 5, l = t & 31;
#pragma unroll
    for (int r = 0; r < ITILE; r++) {
        float m = -1e30f;
#pragma unroll
        for (int k = 0; k < 8; k++) m = fmaxf(m, attn_s[r][w][l + 32 * k]);
#pragma unroll
        for (int o = 16; o > 0; o >>= 1) m = fmaxf(m, __shfl_xor_sync(0xffffffffu, m, o));
        if (l == 0) red[w] = m;
        __syncthreads();
#pragma unroll
        for (int h = 0; h < H; h++)
            attn_s[r][h][t] = __expf(lg[r][h] - red[h]);
        __syncthreads();
        float sm = 0.f;
#pragma unroll
        for (int k = 0; k < 8; k++) sm += attn_s[r][w][l + 32 * k];
#pragma unroll
        for (int o = 16; o > 0; o >>= 1) sm += __shfl_xor_sync(0xffffffffu, sm, o);
        if (l == 0) red[w] = 1.0f / sm;
        __syncthreads();
        float* arow = out + AOFF + ((b * H) * S1 + (i0 + r)) * S1 + t;
#pragma unroll
        for (int h = 0; h < H; h++) {
            float a = attn_s[r][h][t] * red[h];
            attn_s[r][h][t] = a;
            arow[h * S1 * S1] = a;
        }
        __syncthreads();
    }

    // ctx = attn @ v
    int hh = t >> 5;
    const float* vp = g_v + b * S1 * D + t;
    float c0 = 0.f, c1 = 0.f, c2 = 0.f, c3 = 0.f;
#pragma unroll 4
    for (int j = 0; j < S1; j++) {
        float vj = vp[j * D];
        c0 = fmaf(attn_s[0][hh][j], vj, c0);
        c1 = fmaf(attn_s[1][hh][j], vj, c1);
        c2 = fmaf(attn_s[2][hh][j], vj, c2);
        c3 = fmaf(attn_s[3][hh][j], vj, c3);
    }
    out[(b * S1 + i0 + 0) * D + t] = c0;
    out[(b * S1 + i0 + 1) * D + t] = c1;
    out[(b * S1 + i0 + 2) * D + t] = c2;
    out[(b * S1 + i0 + 3) * D + t] = c3;
}

// ---------------- launch ----------------
extern "C" void kernel_launch(void* const* d_in, const int* in_sizes, int n_in,
                              void* d_out, int out_size) {
    (void)in_sizes; (void)n_in; (void)out_size;
    const float* desc = (const float*)d_in[0];
    const float* nve  = (const float*)d_in[1];
    const float* kW   = (const float*)d_in[4];
    const float* vW   = (const float*)d_in[6];
    const float* vb   = (const float*)d_in[7];
    const float* eW1  = (const float*)d_in[8];
    const float* eb1  = (const float*)d_in[9];
    const float* lng  = (const float*)d_in[10];
    const float* lnb  = (const float*)d_in[11];
    const float* eW2  = (const float*)d_in[12];
    const float* aW   = (const float*)d_in[14];
    float* out = (float*)d_out;

    k_transpose<<<dim3(256, 3), 256>>>(vW, eW1);
    k_wvec<<<H, 256>>>(kW, eW2, aW);
    k_node<<<B * (S1 / STILE), 256>>>(desc, nve, vb, eb1);
    k_gemmG<<<dim3(S1 / 32, S1 / 64, B), 256>>>();
    k_main<<<B * S1 / ITILE, 256>>>(lng, lnb, out);
}

// round 7
// speedup vs baseline: 1.5032x; 1.2409x over previous
#include <cuda_runtime.h>

typedef unsigned long long ull;

__device__ __forceinline__ ull ffma2(ull a, ull b, ull c) {
    ull d; asm("fma.rn.f32x2 %0, %1, %2, %3;" : "=l"(d) : "l"(a), "l"(b), "l"(c)); return d;
}
__device__ __forceinline__ ull fadd2(ull a, ull b) {
    ull d; asm("add.rn.f32x2 %0, %1, %2;" : "=l"(d) : "l"(a), "l"(b)); return d;
}
__device__ __forceinline__ ull fpack(float lo, float hi) {
    ull d; asm("mov.b64 %0, {%1, %2};" : "=l"(d) : "f"(lo), "f"(hi)); return d;
}
__device__ __forceinline__ void funpack(ull v, float& lo, float& hi) {
    asm("mov.b64 {%0, %1}, %2;" : "=f"(lo), "=f"(hi) : "l"(v));
}

namespace {
constexpr int D  = 256;
constexpr int H  = 8;
constexpr int HD = 32;
constexpr int S  = 255;
constexpr int S1 = 256;
constexpr int B  = 4;
constexpr int AOFF = B * S1 * H * HD;
constexpr int ITILE = 4;
constexpr int STILE = 8;
}

// ---------------- device scratch ----------------
__device__ float2 g_vWT2 [(D/2) * D];   // [k2][c] = (W[2k2][c], W[2k2+1][c]), W = vW^T
__device__ float2 g_W1Ta2[(D/2) * D];
__device__ float2 g_W1Tb2[(D/2) * D];
__device__ float  g_uk[H * D];
__device__ float  g_V2[D * H];          // [c][h]
__device__ float  g_A[B * S1 * D];      // [b][s][c]
__device__ float  g_Brow[B * S1 * D];   // [b][s][c] incl eb1
__device__ float2 g_At2[B * (D/2) * S1];
__device__ float2 g_Bt2[B * (D/2) * S1];
__device__ float  g_v[B * S1 * D];
__device__ float  g_ks[B * H * S1];
__device__ float  g_SA[B * S1];
__device__ float  g_QA[B * S1];
__device__ float  g_SB[B * S1];
__device__ float  g_QB[B * S1];
__device__ float  g_G0[B * S1 * S1];    // partial A.B over k [0,128)
__device__ float  g_G1[B * S1 * S1];    // partial over k [128,256)
__device__ float  g_part0[B * S1 * H * S1];  // partial logits, channel half 0
__device__ float  g_part1[B * S1 * H * S1];  // channel half 1

// ---------------- kernel 0a: coalesced transpose -> paired layout ----------------
__global__ void k_transpose(const float* __restrict__ vW, const float* __restrict__ eW1) {
    int which = blockIdx.z;
    int c0 = blockIdx.y * 32, k20 = blockIdx.x * 32;
    __shared__ float2 tile[32][33];
    int lx = threadIdx.x & 31;   // k2 within tile
    int ly = threadIdx.x >> 5;

#pragma unroll
    for (int cc = ly; cc < 32; cc += 8) {
        int c = c0 + cc, k = (k20 + lx) * 2;
        const float* p = (which == 0) ? vW + c * D + k
                       : (which == 1) ? eW1 + c * 2 * D + k
                                      : eW1 + c * 2 * D + D + k;
        tile[cc][lx] = *(const float2*)p;
    }
    __syncthreads();
    float2* dst = (which == 0) ? g_vWT2 : (which == 1) ? g_W1Ta2 : g_W1Tb2;
#pragma unroll
    for (int cc = ly; cc < 32; cc += 8) {
        int k2 = k20 + cc, c = c0 + lx;
        dst[k2 * D + c] = tile[lx][cc];
    }
}

// ---------------- kernel 0b: fold attention vectors ----------------
__global__ void k_wvec(const float* __restrict__ kW, const float* __restrict__ eW2,
                       const float* __restrict__ aW) {
    int h = blockIdx.x, c = threadIdx.x;
    float ak = 0.f, av = 0.f;
#pragma unroll
    for (int d = 0; d < HD; d++) {
        ak = fmaf(aW[HD + d],     kW [(h * HD + d) * D + c], ak);
        av = fmaf(aW[2 * HD + d], eW2[(h * HD + d) * D + c], av);
    }
    g_uk[h * D + c] = ak;
    g_V2[c * H + h] = av;
}

// ---------------- kernel 1: per-node precompute (f32x2) ----------------
__global__ void __launch_bounds__(256) k_node(
    const float* __restrict__ desc, const float* __restrict__ nve,
    const float* __restrict__ vb,   const float* __restrict__ eb1) {
    int b = blockIdx.x >> 5, s0 = (blockIdx.x & 31) * STILE, c = threadIdx.x;
    __shared__ float nv[STILE][D];
    __shared__ float ds[STILE][D];
    __shared__ float4 wr[8];

#pragma unroll
    for (int r = 0; r < STILE; r++) {
        nv[r][c] = nve[(b * S1 + s0 + r) * D + c];
        ds[r][c] = (s0 + r < S) ? desc[(b * S + s0 + r) * D + c] : 0.f;
    }
    __syncthreads();

    ull accv2[STILE], acca2[STILE], accb2[STILE];
    float vbc = vb[c], eb1c = eb1[c];
#pragma unroll
    for (int r = 0; r < STILE; r++) {
        accv2[r] = fpack(vbc, 0.f);
        acca2[r] = fpack(0.f, 0.f);
        accb2[r] = fpack(eb1c, 0.f);
    }

#pragma unroll 4
    for (int k2 = 0; k2 < D / 2; k2++) {
        float2 w0 = g_vWT2 [k2 * D + c];
        float2 w1 = g_W1Ta2[k2 * D + c];
        float2 w2 = g_W1Tb2[k2 * D + c];
        ull w0u = *(ull*)&w0, w1u = *(ull*)&w1, w2u = *(ull*)&w2;
#pragma unroll
        for (int r = 0; r < STILE; r++) {
            ull nvp = *(const ull*)&nv[r][2 * k2];
            ull dsp = *(const ull*)&ds[r][2 * k2];
            accv2[r] = ffma2(nvp, w0u, accv2[r]);
            acca2[r] = ffma2(dsp, w1u, acca2[r]);
            accb2[r] = ffma2(dsp, w2u, accb2[r]);
        }
    }

    float accv[STILE], acca[STILE], accb[STILE];
#pragma unroll
    for (int r = 0; r < STILE; r++) {
        float lo, hi;
        funpack(accv2[r], lo, hi); accv[r] = lo + hi;
        funpack(acca2[r], lo, hi); acca[r] = lo + hi;
        funpack(accb2[r], lo, hi); accb[r] = lo + hi;
    }

    int lane = c & 31, w = c >> 5;
#pragma unroll
    for (int r = 0; r < STILE; r++) {
        int s = s0 + r;
        bool valid = (s < S);
        float a  = valid ? acca[r] : 0.f;
        float bb = valid ? accb[r] : 0.f;
        g_v   [(b * S1 + s) * D + c] = accv[r];
        g_A   [(b * S1 + s) * D + c] = a;
        g_Brow[(b * S1 + s) * D + c] = bb;
        ((float*)g_At2)[((b * 128 + (c >> 1)) * S1 + s) * 2 + (c & 1)] = a;
        ((float*)g_Bt2)[((b * 128 + (c >> 1)) * S1 + s) * 2 + (c & 1)] = bb;

        float4 v4 = make_float4(a, a * a, bb, bb * bb);
#pragma unroll
        for (int o = 16; o > 0; o >>= 1) {
            v4.x += __shfl_xor_sync(0xffffffffu, v4.x, o);
            v4.y += __shfl_xor_sync(0xffffffffu, v4.y, o);
            v4.z += __shfl_xor_sync(0xffffffffu, v4.z, o);
            v4.w += __shfl_xor_sync(0xffffffffu, v4.w, o);
        }
        if (lane == 0) wr[w] = v4;
        __syncthreads();
        if (c == 0) {
            float4 t = wr[0];
#pragma unroll
            for (int q = 1; q < 8; q++) {
                float4 o = wr[q];
                t.x += o.x; t.y += o.y; t.z += o.z; t.w += o.w;
            }
            g_SA[b * S1 + s] = t.x; g_QA[b * S1 + s] = t.y;
            g_SB[b * S1 + s] = t.z; g_QB[b * S1 + s] = t.w;
        }
        __syncthreads();
    }

    // ks: warp w handles row s0+w, all 8 heads
    {
        float kacc[H];
#pragma unroll
        for (int h = 0; h < H; h++) kacc[h] = 0.f;
        for (int k = lane; k < D; k += 32) {
            float n = nv[w][k];
#pragma unroll
            for (int h = 0; h < H; h++) kacc[h] = fmaf(n, g_uk[h * D + k], kacc[h]);
        }
#pragma unroll
        for (int h = 0; h < H; h++) {
#pragma unroll
            for (int o = 16; o > 0; o >>= 1)
                kacc[h] += __shfl_xor_sync(0xffffffffu, kacc[h], o);
            if (lane == 0) g_ks[(b * H + h) * S1 + s0 + w] = kacc[h];
        }
    }
}

// ---------------- kernel 1b: G partials, k-split x2 ----------------
__global__ void __launch_bounds__(256) k_gemmG() {
    int kh = blockIdx.z & 1;
    int b  = blockIdx.z >> 1;
    int i0 = blockIdx.y * 32;
    int j0 = blockIdx.x * 32;
    __shared__ float As[32][33];
    __shared__ float Bs[32][33];
    int t = threadIdx.x;
    int jj = t & 31, ii4 = (t >> 5) * 4;
    int lr = t >> 3, lc = (t & 7) * 4;
    float acc0 = 0.f, acc1 = 0.f, acc2 = 0.f, acc3 = 0.f;

    int kbeg = kh * 128;
    for (int kc = kbeg; kc < kbeg + 128; kc += 32) {
        float4 fa = *(const float4*)&g_A   [(b * S1 + i0 + lr) * D + kc + lc];
        float4 fb = *(const float4*)&g_Brow[(b * S1 + j0 + lr) * D + kc + lc];
        As[lr][lc] = fa.x; As[lr][lc+1] = fa.y; As[lr][lc+2] = fa.z; As[lr][lc+3] = fa.w;
        Bs[lr][lc] = fb.x; Bs[lr][lc+1] = fb.y; Bs[lr][lc+2] = fb.z; Bs[lr][lc+3] = fb.w;
        __syncthreads();
#pragma unroll
        for (int kk = 0; kk < 32; kk++) {
            float bv = Bs[jj][kk];
            acc0 = fmaf(As[ii4 + 0][kk], bv, acc0);
            acc1 = fmaf(As[ii4 + 1][kk], bv, acc1);
            acc2 = fmaf(As[ii4 + 2][kk], bv, acc2);
            acc3 = fmaf(As[ii4 + 3][kk], bv, acc3);
        }
        __syncthreads();
    }
    float* dst = kh ? g_G1 : g_G0;
    float* gp = &dst[(b * S1 + i0 + ii4) * S1 + j0 + jj];
    gp[0 * S1] = acc0; gp[1 * S1] = acc1; gp[2 * S1] = acc2; gp[3 * S1] = acc3;
}

// ---------------- kernel 2a: partial logits (channel-split) ----------------
template <bool CLS>
__device__ __forceinline__ void edge_loop(
    int base, const long long* __restrict__ btp, const long long* __restrict__ atp,
    const float (*As4)[D], const ull* gp2, const ull* bp2,
    const ulonglong2* V2u, const ull* rstd2, const ull* nmu2,
    ull acc01[ITILE], ull acc23[ITILE], ull acc45[ITILE], ull acc67[ITILE]) {
#pragma unroll 2
    for (int cc = 0; cc < 64; cc++) {
        int c2 = base + cc;
        ull bt2 = (ull)btp[c2 * S1];
        ull acls = 0;
        if (CLS) acls = (ull)atp[c2 * S1];
        ull g2 = gp2[c2], b2 = bp2[c2];
        ulonglong2 p0 = V2u[4 * c2 + 0], p1 = V2u[4 * c2 + 1];
        ulonglong2 p2 = V2u[4 * c2 + 2], p3 = V2u[4 * c2 + 3];
#pragma unroll
        for (int r = 0; r < ITILE; r++) {
            ull a2 = (CLS && r == 0) ? acls : *(const ull*)&As4[r][2 * c2];
            ull x2 = fadd2(a2, bt2);
            ull t2 = ffma2(x2, rstd2[r], nmu2[r]);
            ull y2 = ffma2(t2, g2, b2);
            float y0, y1; funpack(y2, y0, y1);
            y0 = fmaxf(y0, 0.f); y1 = fmaxf(y1, 0.f);
            ull yy0 = fpack(y0, y0), yy1 = fpack(y1, y1);
            acc01[r] = ffma2(yy0, p0.x, acc01[r]);
            acc23[r] = ffma2(yy0, p0.y, acc23[r]);
            acc45[r] = ffma2(yy0, p1.x, acc45[r]);
            acc67[r] = ffma2(yy0, p1.y, acc67[r]);
            acc01[r] = ffma2(yy1, p2.x, acc01[r]);
            acc23[r] = ffma2(yy1, p2.y, acc23[r]);
            acc45[r] = ffma2(yy1, p3.x, acc45[r]);
            acc67[r] = ffma2(yy1, p3.y, acc67[r]);
        }
    }
}

__global__ void __launch_bounds__(256) k_logits(
    const float* __restrict__ lng, const float* __restrict__ lnb) {
    int i0 = blockIdx.x * ITILE;
    int b  = blockIdx.y;
    int half = blockIdx.z;
    int t = threadIdx.x;
    bool hasCls = (i0 == 0);

    __shared__ float As4[ITILE][D];
    __shared__ ull gp2[D / 2];
    __shared__ ull bp2[D / 2];
    __shared__ ulonglong2 V2u[2 * D];

#pragma unroll
    for (int r = 0; r < ITILE; r++) {
        int i = i0 + r;
        As4[r][t] = (i > 0) ? g_A[(b * S1 + i - 1) * D + t] : 0.f;
    }
    if (t < 128) {
        gp2[t] = fpack(lng[2 * t], lng[2 * t + 1]);
        bp2[t] = fpack(lnb[2 * t], lnb[2 * t + 1]);
    }
    {
        const ulonglong2* src = (const ulonglong2*)g_V2;
        V2u[t] = src[t]; V2u[t + 256] = src[t + 256];
    }
    __syncthreads();

    int jn = (t > 0) ? t - 1 : 0;
    float sb = g_SB[b * S1 + jn], qb = g_QB[b * S1 + jn];
    ull rstd2[ITILE], nmu2[ITILE];
#pragma unroll
    for (int r = 0; r < ITILE; r++) {
        int i = i0 + r;
        float sa, qa, gij;
        if (i == 0) {
            sa = g_SA[b * S1 + jn]; qa = g_QA[b * S1 + jn];
            gij = g_G0[(b * S1 + jn) * S1 + jn] + g_G1[(b * S1 + jn) * S1 + jn];
        } else {
            sa = g_SA[b * S1 + i - 1]; qa = g_QA[b * S1 + i - 1];
            gij = g_G0[(b * S1 + i - 1) * S1 + jn] + g_G1[(b * S1 + i - 1) * S1 + jn];
        }
        const float invD = 1.0f / D;
        float m = (sa + sb) * invD;
        float var = fmaf(2.f, gij, qa + qb) * invD - m * m;
        float rs = rsqrtf(var + 1e-5f);
        rstd2[r] = fpack(rs, rs);
        float nm = -m * rs;
        nmu2[r] = fpack(nm, nm);
    }

    const long long* btp = (const long long*)g_Bt2 + (long long)(b * 128) * S1 + jn;
    const long long* atp = (const long long*)g_At2 + (long long)(b * 128) * S1 + jn;

    ull acc01[ITILE], acc23[ITILE], acc45[ITILE], acc67[ITILE];
    ull z = fpack(0.f, 0.f);
#pragma unroll
    for (int r = 0; r < ITILE; r++) { acc01[r] = z; acc23[r] = z; acc45[r] = z; acc67[r] = z; }

    int base = half * 64;
    if (hasCls) edge_loop<true >(base, btp, atp, As4, gp2, bp2, V2u, rstd2, nmu2, acc01, acc23, acc45, acc67);
    else        edge_loop<false>(base, btp, atp, As4, gp2, bp2, V2u, rstd2, nmu2, acc01, acc23, acc45, acc67);

    float* dst = half ? g_part1 : g_part0;
#pragma unroll
    for (int r = 0; r < ITILE; r++) {
        float l0, l1, l2, l3, l4, l5, l6, l7;
        funpack(acc01[r], l0, l1); funpack(acc23[r], l2, l3);
        funpack(acc45[r], l4, l5); funpack(acc67[r], l6, l7);
        float hv[H] = {l0, l1, l2, l3, l4, l5, l6, l7};
        float* pp = dst + ((b * S1 + i0 + r) * H) * S1 + t;
#pragma unroll
        for (int h = 0; h < H; h++) pp[h * S1] = hv[h];
    }
}

// ---------------- kernel 2b: softmax + context ----------------
__global__ void __launch_bounds__(256) k_smax(float* __restrict__ out) {
    int b = blockIdx.x >> 8, i = blockIdx.x & 255;
    int t = threadIdx.x;
    __shared__ float attn_s[H][S1];
    __shared__ float red[H];

    const float* p0 = g_part0 + ((b * S1 + i) * H) * S1 + t;
    const float* p1 = g_part1 + ((b * S1 + i) * H) * S1 + t;
    const float* ksp = g_ks + b * H * S1 + t;

    float lg[H];
#pragma unroll
    for (int h = 0; h < H; h++) {
        lg[h] = (t > 0) ? p0[h * S1] + p1[h * S1] + ksp[h * S1] : -1e30f;
        attn_s[h][t] = lg[h];
    }
    __syncthreads();

    int w = t >> 5, l = t & 31;
    float m = -1e30f;
#pragma unroll
    for (int k = 0; k < 8; k++) m = fmaxf(m, attn_s[w][l + 32 * k]);
#pragma unroll
    for (int o = 16; o > 0; o >>= 1) m = fmaxf(m, __shfl_xor_sync(0xffffffffu, m, o));
    if (l == 0) red[w] = m;
    __syncthreads();

    float p[H];
#pragma unroll
    for (int h = 0; h < H; h++) {
        p[h] = (t > 0) ? __expf(lg[h] - red[h]) : 0.f;
        attn_s[h][t] = p[h];
    }
    __syncthreads();

    float sm = 0.f;
#pragma unroll
    for (int k = 0; k < 8; k++) sm += attn_s[w][l + 32 * k];
#pragma unroll
    for (int o = 16; o > 0; o >>= 1) sm += __shfl_xor_sync(0xffffffffu, sm, o);
    if (l == 0) red[w] = 1.0f / sm;
    __syncthreads();

    float* arow = out + AOFF + ((b * H) * S1 + i) * S1 + t;
#pragma unroll
    for (int h = 0; h < H; h++) {
        float a = p[h] * red[h];
        attn_s[h][t] = a;
        arow[h * S1 * S1] = a;
    }
    __syncthreads();

    int hh = t >> 5;
    const float* vp = g_v + b * S1 * D + t;
    float acc = 0.f;
#pragma unroll 8
    for (int j = 0; j < S1; j++) acc = fmaf(attn_s[hh][j], vp[j * D], acc);
    out[(b * S1 + i) * D + t] = acc;
}

// ---------------- launch ----------------
extern "C" void kernel_launch(void* const* d_in, const int* in_sizes, int n_in,
                              void* d_out, int out_size) {
    (void)in_sizes; (void)n_in; (void)out_size;
    const float* desc = (const float*)d_in[0];
    const float* nve  = (const float*)d_in[1];
    const float* kW   = (const float*)d_in[4];
    const float* vW   = (const float*)d_in[6];
    const float* vb   = (const float*)d_in[7];
    const float* eW1  = (const float*)d_in[8];
    const float* eb1  = (const float*)d_in[9];
    const float* lng  = (const float*)d_in[10];
    const float* lnb  = (const float*)d_in[11];
    const float* eW2  = (const float*)d_in[12];
    const float* aW   = (const float*)d_in[14];
    float* out = (float*)d_out;

    k_transpose<<<dim3(4, 8, 3), 256>>>(vW, eW1);
    k_wvec<<<H, 256>>>(kW, eW2, aW);
    k_node<<<B * 32, 256>>>(desc, nve, vb, eb1);
    k_gemmG<<<dim3(8, 8, B * 2), 256>>>();
    k_logits<<<dim3(S1 / ITILE, B, 2), 256>>>(lng, lnb);
    k_smax<<<B * S1, 256>>>(out);
}

// round 10
// speedup vs baseline: 1.5072x; 1.0026x over previous
#include <cuda_runtime.h>

typedef unsigned long long ull;

__device__ __forceinline__ ull ffma2(ull a, ull b, ull c) {
    ull d; asm("fma.rn.f32x2 %0, %1, %2, %3;" : "=l"(d) : "l"(a), "l"(b), "l"(c)); return d;
}
__device__ __forceinline__ ull fadd2(ull a, ull b) {
    ull d; asm("add.rn.f32x2 %0, %1, %2;" : "=l"(d) : "l"(a), "l"(b)); return d;
}
__device__ __forceinline__ ull fpack(float lo, float hi) {
    ull d; asm("mov.b64 %0, {%1, %2};" : "=l"(d) : "f"(lo), "f"(hi)); return d;
}
__device__ __forceinline__ void funpack(ull v, float& lo, float& hi) {
    asm("mov.b64 {%0, %1}, %2;" : "=f"(lo), "=f"(hi) : "l"(v));
}

namespace {
constexpr int D  = 256;
constexpr int H  = 8;
constexpr int HD = 32;
constexpr int S  = 255;
constexpr int S1 = 256;
constexpr int B  = 4;
constexpr int AOFF = B * S1 * H * HD;
constexpr int ITILE = 4;
constexpr int STILE = 8;
}

// ---------------- device scratch ----------------
__device__ float2 g_vWT2 [(D/2) * D];
__device__ float2 g_W1Ta2[(D/2) * D];
__device__ float2 g_W1Tb2[(D/2) * D];
__device__ float  g_uk[H * D];
__device__ float  g_V2[D * H];
__device__ float  g_A[B * S1 * D];
__device__ float  g_Brow[B * S1 * D];
__device__ float2 g_At2[B * (D/2) * S1];
__device__ float2 g_Bt2[B * (D/2) * S1];
__device__ float  g_v[B * S1 * D];
__device__ float  g_ks[B * H * S1];
__device__ float  g_SA[B * S1];
__device__ float  g_QA[B * S1];
__device__ float  g_SB[B * S1];
__device__ float  g_QB[B * S1];
__device__ float  g_G0[B * S1 * S1];
__device__ float  g_G1[B * S1 * S1];
__device__ float  g_part0[B * S1 * H * S1];
__device__ float  g_part1[B * S1 * H * S1];

// ---------------- kernel 0a: coalesced transpose -> paired layout ----------------
__global__ void k_transpose(const float* __restrict__ vW, const float* __restrict__ eW1) {
    int which = blockIdx.z;
    int c0 = blockIdx.y * 32, k20 = blockIdx.x * 32;
    __shared__ float2 tile[32][33];
    int lx = threadIdx.x & 31;
    int ly = threadIdx.x >> 5;

#pragma unroll
    for (int cc = ly; cc < 32; cc += 8) {
        int c = c0 + cc, k = (k20 + lx) * 2;
        const float* p = (which == 0) ? vW + c * D + k
                       : (which == 1) ? eW1 + c * 2 * D + k
                                      : eW1 + c * 2 * D + D + k;
        tile[cc][lx] = *(const float2*)p;
    }
    __syncthreads();
    float2* dst = (which == 0) ? g_vWT2 : (which == 1) ? g_W1Ta2 : g_W1Tb2;
#pragma unroll
    for (int cc = ly; cc < 32; cc += 8) {
        int k2 = k20 + cc, c = c0 + lx;
        dst[k2 * D + c] = tile[lx][cc];
    }
}

// ---------------- kernel 0b: fold attention vectors ----------------
__global__ void k_wvec(const float* __restrict__ kW, const float* __restrict__ eW2,
                       const float* __restrict__ aW) {
    int h = blockIdx.x, c = threadIdx.x;
    float ak = 0.f, av = 0.f;
#pragma unroll
    for (int d = 0; d < HD; d++) {
        ak = fmaf(aW[HD + d],     kW [(h * HD + d) * D + c], ak);
        av = fmaf(aW[2 * HD + d], eW2[(h * HD + d) * D + c], av);
    }
    g_uk[h * D + c] = ak;
    g_V2[c * H + h] = av;
}

// ---------------- kernel 1: per-node precompute (f32x2) ----------------
__global__ void __launch_bounds__(256) k_node(
    const float* __restrict__ desc, const float* __restrict__ nve,
    const float* __restrict__ vb,   const float* __restrict__ eb1) {
    int b = blockIdx.x >> 5, s0 = (blockIdx.x & 31) * STILE, c = threadIdx.x;
    __shared__ float nv[STILE][D];
    __shared__ float ds[STILE][D];
    __shared__ float4 wr[8];

#pragma unroll
    for (int r = 0; r < STILE; r++) {
        nv[r][c] = nve[(b * S1 + s0 + r) * D + c];
        ds[r][c] = (s0 + r < S) ? desc[(b * S + s0 + r) * D + c] : 0.f;
    }
    __syncthreads();

    ull accv2[STILE], acca2[STILE], accb2[STILE];
    float vbc = vb[c], eb1c = eb1[c];
#pragma unroll
    for (int r = 0; r < STILE; r++) {
        accv2[r] = fpack(vbc, 0.f);
        acca2[r] = fpack(0.f, 0.f);
        accb2[r] = fpack(eb1c, 0.f);
    }

#pragma unroll 4
    for (int k2 = 0; k2 < D / 2; k2++) {
        float2 w0 = g_vWT2 [k2 * D + c];
        float2 w1 = g_W1Ta2[k2 * D + c];
        float2 w2 = g_W1Tb2[k2 * D + c];
        ull w0u = *(ull*)&w0, w1u = *(ull*)&w1, w2u = *(ull*)&w2;
#pragma unroll
        for (int r = 0; r < STILE; r++) {
            ull nvp = *(const ull*)&nv[r][2 * k2];
            ull dsp = *(const ull*)&ds[r][2 * k2];
            accv2[r] = ffma2(nvp, w0u, accv2[r]);
            acca2[r] = ffma2(dsp, w1u, acca2[r]);
            accb2[r] = ffma2(dsp, w2u, accb2[r]);
        }
    }

    float accv[STILE], acca[STILE], accb[STILE];
#pragma unroll
    for (int r = 0; r < STILE; r++) {
        float lo, hi;
        funpack(accv2[r], lo, hi); accv[r] = lo + hi;
        funpack(acca2[r], lo, hi); acca[r] = lo + hi;
        funpack(accb2[r], lo, hi); accb[r] = lo + hi;
    }

    int lane = c & 31, w = c >> 5;
#pragma unroll
    for (int r = 0; r < STILE; r++) {
        int s = s0 + r;
        bool valid = (s < S);
        float a  = valid ? acca[r] : 0.f;
        float bb = valid ? accb[r] : 0.f;
        g_v   [(b * S1 + s) * D + c] = accv[r];
        g_A   [(b * S1 + s) * D + c] = a;
        g_Brow[(b * S1 + s) * D + c] = bb;
        ((float*)g_At2)[((b * 128 + (c >> 1)) * S1 + s) * 2 + (c & 1)] = a;
        ((float*)g_Bt2)[((b * 128 + (c >> 1)) * S1 + s) * 2 + (c & 1)] = bb;

        float4 v4 = make_float4(a, a * a, bb, bb * bb);
#pragma unroll
        for (int o = 16; o > 0; o >>= 1) {
            v4.x += __shfl_xor_sync(0xffffffffu, v4.x, o);
            v4.y += __shfl_xor_sync(0xffffffffu, v4.y, o);
            v4.z += __shfl_xor_sync(0xffffffffu, v4.z, o);
            v4.w += __shfl_xor_sync(0xffffffffu, v4.w, o);
        }
        if (lane == 0) wr[w] = v4;
        __syncthreads();
        if (c == 0) {
            float4 t = wr[0];
#pragma unroll
            for (int q = 1; q < 8; q++) {
                float4 o = wr[q];
                t.x += o.x; t.y += o.y; t.z += o.z; t.w += o.w;
            }
            g_SA[b * S1 + s] = t.x; g_QA[b * S1 + s] = t.y;
            g_SB[b * S1 + s] = t.z; g_QB[b * S1 + s] = t.w;
        }
        __syncthreads();
    }

    {
        float kacc[H];
#pragma unroll
        for (int h = 0; h < H; h++) kacc[h] = 0.f;
        for (int k = lane; k < D; k += 32) {
            float n = nv[w][k];
#pragma unroll
            for (int h = 0; h < H; h++) kacc[h] = fmaf(n, g_uk[h * D + k], kacc[h]);
        }
#pragma unroll
        for (int h = 0; h < H; h++) {
#pragma unroll
            for (int o = 16; o > 0; o >>= 1)
                kacc[h] += __shfl_xor_sync(0xffffffffu, kacc[h], o);
            if (lane == 0) g_ks[(b * H + h) * S1 + s0 + w] = kacc[h];
        }
    }
}

// ---------------- kernel 1b: G partials, k-split x2; 2 LDS : 4 FFMA inner ----------------
__global__ void __launch_bounds__(256) k_gemmG() {
    int kh = blockIdx.z & 1;
    int b  = blockIdx.z >> 1;
    int i0 = blockIdx.y * 32;
    int j0 = blockIdx.x * 32;
    __shared__ float As[32][36];   // [i][k]
    __shared__ float Bs[32][36];   // [k][j]  (transposed store)
    int t = threadIdx.x;
    int jj4 = (t & 7) * 4, ii = t >> 3;  // output: row ii, cols jj4..jj4+3
    int lr = t >> 3, lc = (t & 7) * 4;   // loader decomposition
    float4 acc = make_float4(0.f, 0.f, 0.f, 0.f);

    int kbeg = kh * 128;
    for (int kc = kbeg; kc < kbeg + 128; kc += 32) {
        float4 fa = *(const float4*)&g_A   [(b * S1 + i0 + lr) * D + kc + lc];
        float4 fb = *(const float4*)&g_Brow[(b * S1 + j0 + lr) * D + kc + lc];
        *(float4*)&As[lr][lc] = fa;                       // natural [i][k]
        Bs[lc + 0][lr] = fb.x; Bs[lc + 1][lr] = fb.y;     // transpose [k][j]
        Bs[lc + 2][lr] = fb.z; Bs[lc + 3][lr] = fb.w;
        __syncthreads();
#pragma unroll
        for (int kk = 0; kk < 32; kk++) {
            float av = As[ii][kk];                        // broadcast
            float4 bv = *(const float4*)&Bs[kk][jj4];     // conflict-free LDS.128
            acc.x = fmaf(av, bv.x, acc.x);
            acc.y = fmaf(av, bv.y, acc.y);
            acc.z = fmaf(av, bv.z, acc.z);
            acc.w = fmaf(av, bv.w, acc.w);
        }
        __syncthreads();
    }
    float* dst = kh ? g_G1 : g_G0;
    *(float4*)&dst[(b * S1 + i0 + ii) * S1 + j0 + jj4] = acc;
}

// ---------------- kernel 2a: partial logits (channel-split) ----------------
template <bool CLS>
__device__ __forceinline__ void edge_loop(
    int base, const long long* __restrict__ btp, const long long* __restrict__ atp,
    const float (*As4)[D], const ull* gp2, const ull* bp2,
    const ulonglong2* V2u, const ull* rstd2, const ull* nmu2,
    ull acc01[ITILE], ull acc23[ITILE], ull acc45[ITILE], ull acc67[ITILE]) {
#pragma unroll 2
    for (int cc = 0; cc < 64; cc++) {
        int c2 = base + cc;
        ull bt2 = (ull)btp[c2 * S1];
        ull acls = 0;
        if (CLS) acls = (ull)atp[c2 * S1];
        ull g2 = gp2[c2], b2 = bp2[c2];
        ulonglong2 p0 = V2u[4 * c2 + 0], p1 = V2u[4 * c2 + 1];
        ulonglong2 p2 = V2u[4 * c2 + 2], p3 = V2u[4 * c2 + 3];
#pragma unroll
        for (int r = 0; r < ITILE; r++) {
            ull a2 = (CLS && r == 0) ? acls : *(const ull*)&As4[r][2 * c2];
            ull x2 = fadd2(a2, bt2);
            ull t2 = ffma2(x2, rstd2[r], nmu2[r]);
            ull y2 = ffma2(t2, g2, b2);
            float y0, y1; funpack(y2, y0, y1);
            y0 = fmaxf(y0, 0.f); y1 = fmaxf(y1, 0.f);
            ull yy0 = fpack(y0, y0), yy1 = fpack(y1, y1);
            acc01[r] = ffma2(yy0, p0.x, acc01[r]);
            acc23[r] = ffma2(yy0, p0.y, acc23[r]);
            acc45[r] = ffma2(yy0, p1.x, acc45[r]);
            acc67[r] = ffma2(yy0, p1.y, acc67[r]);
            acc01[r] = ffma2(yy1, p2.x, acc01[r]);
            acc23[r] = ffma2(yy1, p2.y, acc23[r]);
            acc45[r] = ffma2(yy1, p3.x, acc45[r]);
            acc67[r] = ffma2(yy1, p3.y, acc67[r]);
        }
    }
}

__global__ void __launch_bounds__(256) k_logits(
    const float* __restrict__ lng, const float* __restrict__ lnb) {
    int i0 = blockIdx.x * ITILE;
    int b  = blockIdx.y;
    int half = blockIdx.z;
    int t = threadIdx.x;
    bool hasCls = (i0 == 0);

    __shared__ float As4[ITILE][D];
    __shared__ ull gp2[D / 2];
    __shared__ ull bp2[D / 2];
    __shared__ ulonglong2 V2u[2 * D];

#pragma unroll
    for (int r = 0; r < ITILE; r++) {
        int i = i0 + r;
        As4[r][t] = (i > 0) ? g_A[(b * S1 + i - 1) * D + t] : 0.f;
    }
    if (t < 128) {
        gp2[t] = fpack(lng[2 * t], lng[2 * t + 1]);
        bp2[t] = fpack(lnb[2 * t], lnb[2 * t + 1]);
    }
    {
        const ulonglong2* src = (const ulonglong2*)g_V2;
        V2u[t] = src[t]; V2u[t + 256] = src[t + 256];
    }
    __syncthreads();

    int jn = (t > 0) ? t - 1 : 0;
    float sb = g_SB[b * S1 + jn], qb = g_QB[b * S1 + jn];
    ull rstd2[ITILE], nmu2[ITILE];
#pragma unroll
    for (int r = 0; r < ITILE; r++) {
        int i = i0 + r;
        float sa, qa, gij;
        if (i == 0) {
            sa = g_SA[b * S1 + jn]; qa = g_QA[b * S1 + jn];
            gij = g_G0[(b * S1 + jn) * S1 + jn] + g_G1[(b * S1 + jn) * S1 + jn];
        } else {
            sa = g_SA[b * S1 + i - 1]; qa = g_QA[b * S1 + i - 1];
            gij = g_G0[(b * S1 + i - 1) * S1 + jn] + g_G1[(b * S1 + i - 1) * S1 + jn];
        }
        const float invD = 1.0f / D;
        float m = (sa + sb) * invD;
        float var = fmaf(2.f, gij, qa + qb) * invD - m * m;
        float rs = rsqrtf(var + 1e-5f);
        rstd2[r] = fpack(rs, rs);
        float nm = -m * rs;
        nmu2[r] = fpack(nm, nm);
    }

    const long long* btp = (const long long*)g_Bt2 + (long long)(b * 128) * S1 + jn;
    const long long* atp = (const long long*)g_At2 + (long long)(b * 128) * S1 + jn;

    ull acc01[ITILE], acc23[ITILE], acc45[ITILE], acc67[ITILE];
    ull z = fpack(0.f, 0.f);
#pragma unroll
    for (int r = 0; r < ITILE; r++) { acc01[r] = z; acc23[r] = z; acc45[r] = z; acc67[r] = z; }

    int base = half * 64;
    if (hasCls) edge_loop<true >(base, btp, atp, As4, gp2, bp2, V2u, rstd2, nmu2, acc01, acc23, acc45, acc67);
    else        edge_loop<false>(base, btp, atp, As4, gp2, bp2, V2u, rstd2, nmu2, acc01, acc23, acc45, acc67);

    float* dst = half ? g_part1 : g_part0;
#pragma unroll
    for (int r = 0; r < ITILE; r++) {
        float l0, l1, l2, l3, l4, l5, l6, l7;
        funpack(acc01[r], l0, l1); funpack(acc23[r], l2, l3);
        funpack(acc45[r], l4, l5); funpack(acc67[r], l6, l7);
        float hv[H] = {l0, l1, l2, l3, l4, l5, l6, l7};
        float* pp = dst + ((b * S1 + i0 + r) * H) * S1 + t;
#pragma unroll
        for (int h = 0; h < H; h++) pp[h * S1] = hv[h];
    }
}

// ---------------- kernel 2b: softmax + context (float4 j-split ctx) ----------------
__global__ void __launch_bounds__(256) k_smax(float* __restrict__ out) {
    int b = blockIdx.x >> 8, i = blockIdx.x & 255;
    int t = threadIdx.x;
    __shared__ float attn_s[H][S1 + 8];   // pad: 4-head broadcast reads conflict-free
    __shared__ float red[H];
    __shared__ float4 part4[4][64];

    const float* p0 = g_part0 + ((b * S1 + i) * H) * S1 + t;
    const float* p1 = g_part1 + ((b * S1 + i) * H) * S1 + t;
    const float* ksp = g_ks + b * H * S1 + t;

    float lg[H];
#pragma unroll
    for (int h = 0; h < H; h++) {
        lg[h] = (t > 0) ? p0[h * S1] + p1[h * S1] + ksp[h * S1] : -1e30f;
        attn_s[h][t] = lg[h];
    }
    __syncthreads();

    int w = t >> 5, l = t & 31;
    float m = -1e30f;
#pragma unroll
    for (int k = 0; k < 8; k++) m = fmaxf(m, attn_s[w][l + 32 * k]);
#pragma unroll
    for (int o = 16; o > 0; o >>= 1) m = fmaxf(m, __shfl_xor_sync(0xffffffffu, m, o));
    if (l == 0) red[w] = m;
    __syncthreads();

    float p[H];
#pragma unroll
    for (int h = 0; h < H; h++) {
        p[h] = (t > 0) ? __expf(lg[h] - red[h]) : 0.f;
        attn_s[h][t] = p[h];
    }
    __syncthreads();

    float sm = 0.f;
#pragma unroll
    for (int k = 0; k < 8; k++) sm += attn_s[w][l + 32 * k];
#pragma unroll
    for (int o = 16; o > 0; o >>= 1) sm += __shfl_xor_sync(0xffffffffu, sm, o);
    if (l == 0) red[w] = 1.0f / sm;
    __syncthreads();

    float* arow = out + AOFF + ((b * H) * S1 + i) * S1 + t;
#pragma unroll
    for (int h = 0; h < H; h++) {
        float a = p[h] * red[h];
        attn_s[h][t] = a;
        arow[h * S1 * S1] = a;
    }
    __syncthreads();

    // ctx: thread (jg, cg): 4 channels (float4), 64 j's; reduce 4 partials
    int jg = t >> 6, cg = t & 63, hh = cg >> 3;
    const float4* vp4 = (const float4*)(g_v + (size_t)b * S1 * D) + cg;
    float4 a4 = make_float4(0.f, 0.f, 0.f, 0.f);
    int jbeg = jg * 64;
#pragma unroll 4
    for (int j = jbeg; j < jbeg + 64; j++) {
        float wgt = attn_s[hh][j];
        float4 v4 = vp4[(size_t)j * 64];
        a4.x = fmaf(wgt, v4.x, a4.x);
        a4.y = fmaf(wgt, v4.y, a4.y);
        a4.z = fmaf(wgt, v4.z, a4.z);
        a4.w = fmaf(wgt, v4.w, a4.w);
    }
    part4[jg][cg] = a4;
    __syncthreads();
    if (t < 64) {
        float4 r0 = part4[0][t], r1 = part4[1][t], r2 = part4[2][t], r3 = part4[3][t];
        r0.x += r1.x + r2.x + r3.x;
        r0.y += r1.y + r2.y + r3.y;
        r0.z += r1.z + r2.z + r3.z;
        r0.w += r1.w + r2.w + r3.w;
        ((float4*)(out + ((size_t)(b * S1) + i) * D))[t] = r0;
    }
}

// ---------------- launch ----------------
extern "C" void kernel_launch(void* const* d_in, const int* in_sizes, int n_in,
                              void* d_out, int out_size) {
    (void)in_sizes; (void)n_in; (void)out_size;
    const float* desc = (const float*)d_in[0];
    const float* nve  = (const float*)d_in[1];
    const float* kW   = (const float*)d_in[4];
    const float* vW   = (const float*)d_in[6];
    const float* vb   = (const float*)d_in[7];
    const float* eW1  = (const float*)d_in[8];
    const float* eb1  = (const float*)d_in[9];
    const float* lng  = (const float*)d_in[10];
    const float* lnb  = (const float*)d_in[11];
    const float* eW2  = (const float*)d_in[12];
    const float* aW   = (const float*)d_in[14];
    float* out = (float*)d_out;

    k_transpose<<<dim3(4, 8, 3), 256>>>(vW, eW1);
    k_wvec<<<H, 256>>>(kW, eW2, aW);
    k_node<<<B * 32, 256>>>(desc, nve, vb, eb1);
    k_gemmG<<<dim3(8, 8, B * 2), 256>>>();
    k_logits<<<dim3(S1 / ITILE, B, 2), 256>>>(lng, lnb);
    k_smax<<<B * S1, 256>>>(out);
}